// round 10
// baseline (speedup 1.0000x reference)
#include <cuda_runtime.h>
#include <cstdint>
#include <math.h>

// Binary MLP B=16384, D=H=1024, C=10 — all-popc path, register-lean.
// Bit-packed XOR + balanced CSA(q=16); BN+sign folded to integer threshold.
// Single row per iteration with inline XOR (low live regs -> high occupancy).

#define NB       16384
#define KW       32
#define HN       1024
#define ROWS_PB  64
#define GRP_PB   8
#define THREADS  256

__device__ unsigned g_act[2][NB * KW];     // ping-pong packed activations
__device__ unsigned g_wt[3][KW * HN];      // packed hidden weights [word j][neuron n]
__device__ unsigned g_w4[10 * KW];         // packed output weights
__device__ int2     g_thri[3 * HN];        // (thr, neg) per neuron per layer

__device__ __forceinline__ unsigned lop3_96(unsigned a, unsigned b, unsigned c) { // a^b^c
    unsigned r;
    asm("lop3.b32 %0, %1, %2, %3, 0x96;" : "=r"(r) : "r"(a), "r"(b), "r"(c));
    return r;
}
__device__ __forceinline__ unsigned lop3_e8(unsigned a, unsigned b, unsigned c) { // maj
    unsigned r;
    asm("lop3.b32 %0, %1, %2, %3, 0xE8;" : "=r"(r) : "r"(a), "r"(b), "r"(c));
    return r;
}
#define FA(a, b, c, s, cy) { s = lop3_96(a, b, c); cy = lop3_e8(a, b, c); }

// ======================= ballot-based prep kernels =======================
// one thread per element; ballot produces packed words directly.
__global__ void pack_x_kernel(const float* __restrict__ x) {
    int t = blockIdx.x * blockDim.x + threadIdx.x;     // NB*1024 threads
    int k = t >> 5;                                     // word index (NB*KW)
    unsigned bit = (x[t] >= 0.5f) ? 1u : 0u;            // sign(2x-1) >= 0
    unsigned word = __ballot_sync(0xffffffffu, bit);
    if ((t & 31) == 0) g_act[0][k] = word;
}

__global__ void pack_w_kernel(const float* __restrict__ W, int widx) {
    int t = blockIdx.x * blockDim.x + threadIdx.x;     // HN*1024 threads
    int n = t >> 10;                                    // weight row (neuron)
    int j = (t >> 5) & 31;                              // word within row
    unsigned bit = (W[t] >= 0.0f) ? 1u : 0u;
    unsigned word = __ballot_sync(0xffffffffu, bit);
    if ((t & 31) == 0) g_wt[widx][j * HN + n] = word;
}

__global__ void pack_w4_kernel(const float* __restrict__ W4) {
    int t = blockIdx.x * blockDim.x + threadIdx.x;     // 10*1024 threads
    if (t >= 10 * 1024) return;
    unsigned bit = (W4[t] >= 0.0f) ? 1u : 0u;
    unsigned word = __ballot_sync(0xffffffffu, bit);
    if ((t & 31) == 0) g_w4[t >> 5] = word;             // [c][j] contiguous
}

// exact integer thresholds: bit = ((P <= thr) ? 1 : 0) ^ neg
__global__ void thr_kernel(const float* __restrict__ g, const float* __restrict__ b,
                           const float* __restrict__ m, const float* __restrict__ v,
                           int2* __restrict__ out) {
    int n = blockIdx.x * blockDim.x + threadIdx.x;
    if (n >= HN) return;
    double sc = (double)g[n] / sqrt((double)v[n] + 1e-5);
    int thr; int neg;
    if (sc > 0.0) {
        double T = (1024.0 - (double)m[n] + (double)b[n] / sc) * 0.5;
        T = fmin(fmax(T, -2.0e9), 2.0e9);
        thr = (int)floor(T); neg = 0;
    } else if (sc < 0.0) {
        double T = (1024.0 - (double)m[n] + (double)b[n] / sc) * 0.5;
        T = fmin(fmax(T, -2.0e9), 2.0e9);
        thr = (int)ceil(T) - 1; neg = 1;
    } else {
        thr = ((double)b[n] >= 0.0) ? 0x7fffffff : (-0x7fffffff - 1); neg = 0;
    }
    out[n] = make_int2(thr, neg);
}

// ======================= hidden layer =======================
// grid (NB/ROWS_PB, HN/256) = (256, 4); 8 warps, one 32-neuron group each.
// Register-lean: XOR consumed inline by the CSA; chunk-aligned triples.
__global__ void __launch_bounds__(THREADS, 2)
layer_kernel(int src, int dst, int widx, const int2* __restrict__ thrv) {
    __shared__ uint4 sh_a[ROWS_PB][8];

    const int tid  = threadIdx.x;
    const int lane = tid & 31;
    const int wid  = tid >> 5;
    const int row0 = blockIdx.x * ROWS_PB;
    const int grp  = blockIdx.y * GRP_PB + wid;
    const int n    = grp * 32 + lane;

    {   // stage A tile: 64 rows x 32 words = 512 uint4
        const uint4* asrc = reinterpret_cast<const uint4*>(&g_act[src][(size_t)row0 * KW]);
        uint4* adst = &sh_a[0][0];
#pragma unroll
        for (int t = 0; t < ROWS_PB * 8 / THREADS; t++)
            adst[tid + t * THREADS] = asrc[tid + t * THREADS];
    }

    unsigned w[KW];
    const unsigned* wt = &g_wt[widx][0];
#pragma unroll
    for (int j = 0; j < KW; j++) w[j] = wt[j * HN + n];

    const int2 tn  = thrv[n];
    const int  thr = tn.x;
    const unsigned neg = (unsigned)tn.y;
    __syncthreads();

    unsigned* out = &g_act[dst][0];
    for (int r = 0; r < ROWS_PB; ++r) {
        const uint4* sa = sh_a[r];

        // naive popc on words 0..8 (XOR consumed immediately)
        uint4 q = sa[0];
        int pa = __popc(q.x ^ w[0]) + __popc(q.y ^ w[1]);
        int pb = __popc(q.z ^ w[2]) + __popc(q.w ^ w[3]);
        q = sa[1];
        pa += __popc(q.x ^ w[4]) + __popc(q.y ^ w[5]);
        pb += __popc(q.z ^ w[6]) + __popc(q.w ^ w[7]);
        q = sa[2];
        pa += __popc(q.x ^ w[8]);

        // CSA on words 9..31: chunk-aligned triples, 3 saved cross-chunk words
        unsigned s0,c0,s1,c1,s2,c2,s3,c3,s4,c4,s5,c5,s6,c6;
        FA(q.y ^ w[9], q.z ^ w[10], q.w ^ w[11], s0, c0);
        q = sa[3];
        FA(q.x ^ w[12], q.y ^ w[13], q.z ^ w[14], s1, c1);
        unsigned r15 = q.w ^ w[15];
        q = sa[4];
        FA(q.x ^ w[16], q.y ^ w[17], q.z ^ w[18], s2, c2);
        unsigned r19 = q.w ^ w[19];
        q = sa[5];
        FA(q.x ^ w[20], q.y ^ w[21], q.z ^ w[22], s3, c3);
        unsigned r23 = q.w ^ w[23];
        q = sa[6];
        FA(q.x ^ w[24], q.y ^ w[25], q.z ^ w[26], s4, c4);
        unsigned r27 = q.w ^ w[27];
        q = sa[7];
        FA(q.x ^ w[28], q.y ^ w[29], q.z ^ w[30], s5, c5);
        unsigned r31 = q.w ^ w[31];
        FA(r15, r19, r23, s6, c6);

        // weight-1 pool: s0..s6, r27, r31
        unsigned u0,d0,u1,d1,u2,d2,u3,d3;
        FA(s0, s1, s2,   u0, d0);
        FA(s3, s4, s5,   u1, d1);
        FA(s6, r27, r31, u2, d2);
        FA(u0, u1, u2,   u3, d3);
        // weight-2 pool: c0..c6, d0..d3
        unsigned e0,f0,e1,f1,e2,f2,e3,f3,e4,f4;
        FA(c0, c1, c2, e0, f0);
        FA(c3, c4, c5, e1, f1);
        FA(c6, d0, d1, e2, f2);
        FA(e0, e1, e2, e3, f3);
        FA(e3, d2, d3, e4, f4);

        int F = (__popc(f0) + __popc(f1) + __popc(f2)) + (__popc(f3) + __popc(f4));
        int P = (pa + pb) + __popc(u3) + 2 * __popc(e4) + 4 * F;

        unsigned bit = ((P <= thr) ? 1u : 0u) ^ neg;
        unsigned wordbits = __ballot_sync(0xffffffffu, bit != 0u);
        if (lane == 0) out[(size_t)(row0 + r) * KW + grp] = wordbits;
    }
}

// ======================= final layer + TensorNorm =======================
__global__ void final_kernel(const float* __restrict__ tnw, const float* __restrict__ tnb,
                             const float* __restrict__ tnm, const float* __restrict__ tnv,
                             float* __restrict__ out) {
    __shared__ unsigned sw[10 * KW];
    const int tid = threadIdx.x;
    for (int i = tid; i < 10 * KW; i += blockDim.x) sw[i] = g_w4[i];
    __syncthreads();

    int row = blockIdx.x * blockDim.x + tid;
    if (row >= NB) return;

    uint4 a[8];
    const uint4* p = reinterpret_cast<const uint4*>(&g_act[1][(size_t)row * KW]);
#pragma unroll
    for (int i = 0; i < 8; i++) a[i] = p[i];

    float rs = (float)(1.0 / sqrt((double)tnv[0] + 1e-4));
    float wq = tnw[0], bq = tnb[0], mq = tnm[0];

#pragma unroll
    for (int c = 0; c < 10; c++) {
        int P = 0;
#pragma unroll
        for (int i = 0; i < 8; i++) {
            P += __popc(a[i].x ^ sw[c * KW + 4 * i + 0]);
            P += __popc(a[i].y ^ sw[c * KW + 4 * i + 1]);
            P += __popc(a[i].z ^ sw[c * KW + 4 * i + 2]);
            P += __popc(a[i].w ^ sw[c * KW + 4 * i + 3]);
        }
        float s = (float)(1024 - 2 * P);
        out[(size_t)row * 10 + c] = ((s - mq) * rs) * wq + bq;
    }
}

// ======================= launch =======================
extern "C" void kernel_launch(void* const* d_in, const int* in_sizes, int n_in,
                              void* d_out, int out_size) {
    const float* x  = (const float*)d_in[0];
    const float* W1 = (const float*)d_in[1];
    const float* W2 = (const float*)d_in[2];
    const float* W3 = (const float*)d_in[3];
    const float* W4 = (const float*)d_in[4];
    const float* g1 = (const float*)d_in[5],  *b1 = (const float*)d_in[6];
    const float* m1 = (const float*)d_in[7],  *v1 = (const float*)d_in[8];
    const float* g2 = (const float*)d_in[9],  *b2 = (const float*)d_in[10];
    const float* m2 = (const float*)d_in[11], *v2 = (const float*)d_in[12];
    const float* g3 = (const float*)d_in[13], *b3 = (const float*)d_in[14];
    const float* m3 = (const float*)d_in[15], *v3 = (const float*)d_in[16];
    const float* tnw = (const float*)d_in[17], *tnb = (const float*)d_in[18];
    const float* tnm = (const float*)d_in[19], *tnv = (const float*)d_in[20];
    float* out = (float*)d_out;

    void* pt;
    cudaGetSymbolAddress(&pt, g_thri);
    int2* tv = (int2*)pt;

    pack_x_kernel<<<NB * 1024 / 256, 256>>>(x);
    pack_w_kernel<<<HN * 1024 / 256, 256>>>(W1, 0);
    pack_w_kernel<<<HN * 1024 / 256, 256>>>(W2, 1);
    pack_w_kernel<<<HN * 1024 / 256, 256>>>(W3, 2);
    thr_kernel<<<4, 256>>>(g1, b1, m1, v1, tv);
    thr_kernel<<<4, 256>>>(g2, b2, m2, v2, tv + 1024);
    thr_kernel<<<4, 256>>>(g3, b3, m3, v3, tv + 2048);
    pack_w4_kernel<<<40, 256>>>(W4);

    dim3 lgrid(NB / ROWS_PB, HN / (GRP_PB * 32));    // (256, 4)
    layer_kernel<<<lgrid, THREADS>>>(0, 1, 0, tv);
    layer_kernel<<<lgrid, THREADS>>>(1, 0, 1, tv + 1024);
    layer_kernel<<<lgrid, THREADS>>>(0, 1, 2, tv + 2048);

    final_kernel<<<NB / 256, 256>>>(tnw, tnb, tnm, tnv, out);
}

// round 12
// speedup vs baseline: 1.0067x; 1.0067x over previous
#include <cuda_runtime.h>
#include <cstdint>
#include <math.h>

// Binary MLP B=16384, D=H=1024, C=10 — all-popc path.
// Bit-packed XOR + balanced CSA(q=16); BN+sign folded to integer threshold.
// 2 rows/iteration (ILP) with inline-XOR trees (low live regs -> 2 blocks/SM).

#define NB       16384
#define KW       32
#define HN       1024
#define ROWS_PB  64
#define GRP_PB   8
#define THREADS  256

__device__ unsigned g_act[2][NB * KW];     // ping-pong packed activations
__device__ unsigned g_wt[3][KW * HN];      // packed hidden weights [word j][neuron n]
__device__ unsigned g_w4[10 * KW];         // packed output weights
__device__ int2     g_thri[3 * HN];        // (thr, neg) per neuron per layer

__device__ __forceinline__ unsigned lop3_96(unsigned a, unsigned b, unsigned c) { // a^b^c
    unsigned r;
    asm("lop3.b32 %0, %1, %2, %3, 0x96;" : "=r"(r) : "r"(a), "r"(b), "r"(c));
    return r;
}
__device__ __forceinline__ unsigned lop3_e8(unsigned a, unsigned b, unsigned c) { // maj
    unsigned r;
    asm("lop3.b32 %0, %1, %2, %3, 0xE8;" : "=r"(r) : "r"(a), "r"(b), "r"(c));
    return r;
}
#define FA(a, b, c, s, cy) { s = lop3_96(a, b, c); cy = lop3_e8(a, b, c); }

// exact 1024-bit count for one row: 9 naive popc + 23-word CSA (16 FAs, 7 popc)
// XORs consumed inline; low live-register footprint.
__device__ __forceinline__ int count_row(const uint4* __restrict__ sa,
                                         const unsigned* __restrict__ w) {
    uint4 q = sa[0];
    int pa = __popc(q.x ^ w[0]) + __popc(q.y ^ w[1]);
    int pb = __popc(q.z ^ w[2]) + __popc(q.w ^ w[3]);
    q = sa[1];
    pa += __popc(q.x ^ w[4]) + __popc(q.y ^ w[5]);
    pb += __popc(q.z ^ w[6]) + __popc(q.w ^ w[7]);
    q = sa[2];
    pa += __popc(q.x ^ w[8]);

    unsigned s0,c0,s1,c1,s2,c2,s3,c3,s4,c4,s5,c5,s6,c6;
    FA(q.y ^ w[9], q.z ^ w[10], q.w ^ w[11], s0, c0);
    q = sa[3];
    FA(q.x ^ w[12], q.y ^ w[13], q.z ^ w[14], s1, c1);
    unsigned r15 = q.w ^ w[15];
    q = sa[4];
    FA(q.x ^ w[16], q.y ^ w[17], q.z ^ w[18], s2, c2);
    unsigned r19 = q.w ^ w[19];
    q = sa[5];
    FA(q.x ^ w[20], q.y ^ w[21], q.z ^ w[22], s3, c3);
    unsigned r23 = q.w ^ w[23];
    q = sa[6];
    FA(q.x ^ w[24], q.y ^ w[25], q.z ^ w[26], s4, c4);
    unsigned r27 = q.w ^ w[27];
    q = sa[7];
    FA(q.x ^ w[28], q.y ^ w[29], q.z ^ w[30], s5, c5);
    unsigned r31 = q.w ^ w[31];
    FA(r15, r19, r23, s6, c6);

    unsigned u0,d0,u1,d1,u2,d2,u3,d3;
    FA(s0, s1, s2,   u0, d0);
    FA(s3, s4, s5,   u1, d1);
    FA(s6, r27, r31, u2, d2);
    FA(u0, u1, u2,   u3, d3);
    unsigned e0,f0,e1,f1,e2,f2,e3,f3,e4,f4;
    FA(c0, c1, c2, e0, f0);
    FA(c3, c4, c5, e1, f1);
    FA(c6, d0, d1, e2, f2);
    FA(e0, e1, e2, e3, f3);
    FA(e3, d2, d3, e4, f4);

    int F = (__popc(f0) + __popc(f1) + __popc(f2)) + (__popc(f3) + __popc(f4));
    return (pa + pb) + __popc(u3) + 2 * __popc(e4) + 4 * F;
}

// ======================= prep kernels =======================
__global__ void pack_x_kernel(const float* __restrict__ x) {
    int t = blockIdx.x * blockDim.x + threadIdx.x;     // NB*1024 threads
    unsigned bit = (x[t] >= 0.5f) ? 1u : 0u;            // sign(2x-1) >= 0
    unsigned word = __ballot_sync(0xffffffffu, bit);
    if ((t & 31) == 0) g_act[0][t >> 5] = word;
}

__global__ void pack_w_kernel(const float* __restrict__ W, int widx) {
    int t = blockIdx.x * blockDim.x + threadIdx.x;     // HN*1024 threads
    int n = t >> 10;
    int j = (t >> 5) & 31;
    unsigned bit = (W[t] >= 0.0f) ? 1u : 0u;
    unsigned word = __ballot_sync(0xffffffffu, bit);
    if ((t & 31) == 0) g_wt[widx][j * HN + n] = word;
}

__global__ void pack_w4_kernel(const float* __restrict__ W4) {
    int t = blockIdx.x * blockDim.x + threadIdx.x;     // 10*1024 threads
    if (t >= 10 * 1024) return;
    unsigned bit = (W4[t] >= 0.0f) ? 1u : 0u;
    unsigned word = __ballot_sync(0xffffffffu, bit);
    if ((t & 31) == 0) g_w4[t >> 5] = word;
}

// exact integer thresholds: bit = ((P <= thr) ? 1 : 0) ^ neg
__global__ void thr_kernel(const float* __restrict__ g, const float* __restrict__ b,
                           const float* __restrict__ m, const float* __restrict__ v,
                           int2* __restrict__ out) {
    int n = blockIdx.x * blockDim.x + threadIdx.x;
    if (n >= HN) return;
    double sc = (double)g[n] / sqrt((double)v[n] + 1e-5);
    int thr; int neg;
    if (sc > 0.0) {
        double T = (1024.0 - (double)m[n] + (double)b[n] / sc) * 0.5;
        T = fmin(fmax(T, -2.0e9), 2.0e9);
        thr = (int)floor(T); neg = 0;
    } else if (sc < 0.0) {
        double T = (1024.0 - (double)m[n] + (double)b[n] / sc) * 0.5;
        T = fmin(fmax(T, -2.0e9), 2.0e9);
        thr = (int)ceil(T) - 1; neg = 1;
    } else {
        thr = ((double)b[n] >= 0.0) ? 0x7fffffff : (-0x7fffffff - 1); neg = 0;
    }
    out[n] = make_int2(thr, neg);
}

// ======================= hidden layer =======================
// grid (NB/ROWS_PB, HN/256) = (256, 4); 8 warps, one 32-neuron group each;
// 2 rows per iteration, 2 blocks/SM.
__global__ void __launch_bounds__(THREADS, 2)
layer_kernel(int src, int dst, int widx, const int2* __restrict__ thrv) {
    __shared__ uint4 sh_a[ROWS_PB][8];

    const int tid  = threadIdx.x;
    const int lane = tid & 31;
    const int wid  = tid >> 5;
    const int row0 = blockIdx.x * ROWS_PB;
    const int grp  = blockIdx.y * GRP_PB + wid;
    const int n    = grp * 32 + lane;

    {   // stage A tile: 64 rows x 32 words = 512 uint4
        const uint4* asrc = reinterpret_cast<const uint4*>(&g_act[src][(size_t)row0 * KW]);
        uint4* adst = &sh_a[0][0];
#pragma unroll
        for (int t = 0; t < ROWS_PB * 8 / THREADS; t++)
            adst[tid + t * THREADS] = asrc[tid + t * THREADS];
    }

    unsigned w[KW];
    const unsigned* wt = &g_wt[widx][0];
#pragma unroll
    for (int j = 0; j < KW; j++) w[j] = wt[j * HN + n];

    const int2 tn  = thrv[n];
    const int  thr = tn.x;
    const unsigned neg = (unsigned)tn.y;
    __syncthreads();

    unsigned* out = &g_act[dst][0];
    for (int r = 0; r < ROWS_PB; r += 2) {
        int P0 = count_row(sh_a[r],     w);
        int P1 = count_row(sh_a[r + 1], w);

        unsigned bit0 = ((P0 <= thr) ? 1u : 0u) ^ neg;
        unsigned bit1 = ((P1 <= thr) ? 1u : 0u) ^ neg;
        unsigned wb0 = __ballot_sync(0xffffffffu, bit0 != 0u);
        unsigned wb1 = __ballot_sync(0xffffffffu, bit1 != 0u);
        if (lane == 0) {
            out[(size_t)(row0 + r)     * KW + grp] = wb0;
            out[(size_t)(row0 + r + 1) * KW + grp] = wb1;
        }
    }
}

// ======================= final layer + TensorNorm =======================
__global__ void final_kernel(const float* __restrict__ tnw, const float* __restrict__ tnb,
                             const float* __restrict__ tnm, const float* __restrict__ tnv,
                             float* __restrict__ out) {
    __shared__ unsigned sw[10 * KW];
    const int tid = threadIdx.x;
    for (int i = tid; i < 10 * KW; i += blockDim.x) sw[i] = g_w4[i];
    __syncthreads();

    int row = blockIdx.x * blockDim.x + tid;
    if (row >= NB) return;

    uint4 a[8];
    const uint4* p = reinterpret_cast<const uint4*>(&g_act[1][(size_t)row * KW]);
#pragma unroll
    for (int i = 0; i < 8; i++) a[i] = p[i];

    float rs = (float)(1.0 / sqrt((double)tnv[0] + 1e-4));
    float wq = tnw[0], bq = tnb[0], mq = tnm[0];

#pragma unroll
    for (int c = 0; c < 10; c++) {
        int P = 0;
#pragma unroll
        for (int i = 0; i < 8; i++) {
            P += __popc(a[i].x ^ sw[c * KW + 4 * i + 0]);
            P += __popc(a[i].y ^ sw[c * KW + 4 * i + 1]);
            P += __popc(a[i].z ^ sw[c * KW + 4 * i + 2]);
            P += __popc(a[i].w ^ sw[c * KW + 4 * i + 3]);
        }
        float s = (float)(1024 - 2 * P);
        out[(size_t)row * 10 + c] = ((s - mq) * rs) * wq + bq;
    }
}

// ======================= launch =======================
extern "C" void kernel_launch(void* const* d_in, const int* in_sizes, int n_in,
                              void* d_out, int out_size) {
    const float* x  = (const float*)d_in[0];
    const float* W1 = (const float*)d_in[1];
    const float* W2 = (const float*)d_in[2];
    const float* W3 = (const float*)d_in[3];
    const float* W4 = (const float*)d_in[4];
    const float* g1 = (const float*)d_in[5],  *b1 = (const float*)d_in[6];
    const float* m1 = (const float*)d_in[7],  *v1 = (const float*)d_in[8];
    const float* g2 = (const float*)d_in[9],  *b2 = (const float*)d_in[10];
    const float* m2 = (const float*)d_in[11], *v2 = (const float*)d_in[12];
    const float* g3 = (const float*)d_in[13], *b3 = (const float*)d_in[14];
    const float* m3 = (const float*)d_in[15], *v3 = (const float*)d_in[16];
    const float* tnw = (const float*)d_in[17], *tnb = (const float*)d_in[18];
    const float* tnm = (const float*)d_in[19], *tnv = (const float*)d_in[20];
    float* out = (float*)d_out;

    void* pt;
    cudaGetSymbolAddress(&pt, g_thri);
    int2* tv = (int2*)pt;

    pack_x_kernel<<<NB * 1024 / 256, 256>>>(x);
    pack_w_kernel<<<HN * 1024 / 256, 256>>>(W1, 0);
    pack_w_kernel<<<HN * 1024 / 256, 256>>>(W2, 1);
    pack_w_kernel<<<HN * 1024 / 256, 256>>>(W3, 2);
    thr_kernel<<<4, 256>>>(g1, b1, m1, v1, tv);
    thr_kernel<<<4, 256>>>(g2, b2, m2, v2, tv + 1024);
    thr_kernel<<<4, 256>>>(g3, b3, m3, v3, tv + 2048);
    pack_w4_kernel<<<40, 256>>>(W4);

    dim3 lgrid(NB / ROWS_PB, HN / (GRP_PB * 32));    // (256, 4)
    layer_kernel<<<lgrid, THREADS>>>(0, 1, 0, tv);
    layer_kernel<<<lgrid, THREADS>>>(1, 0, 1, tv + 1024);
    layer_kernel<<<lgrid, THREADS>>>(0, 1, 2, tv + 2048);

    final_kernel<<<NB / 256, 256>>>(tnw, tnb, tnm, tnv, out);
}